// round 4
// baseline (speedup 1.0000x reference)
#include <cuda_runtime.h>
#include <math_constants.h>

// Problem constants
#define NPOS 65536   // 64 * 32 * 32 positions
#define DIM  64      // embedding dim
#define KCB  512     // codebook size
#define NCHW_ELEMS 4194304  // 64*64*32*32

typedef unsigned long long ull;

// Scratch (allocation-free: __device__ globals)
__device__ int   g_idx[NPOS];
__device__ int   g_hist[KCB];
__device__ float g_ne[KCB];        // ||e_k||^2 in fp32
__device__ float g_partial[512];

// Packed fp32x2 FMA (Blackwell): per-lane IEEE identical to scalar fmaf.
__device__ __forceinline__ void ffma2(ull& acc, ull a, ull b) {
    asm("fma.rn.f32x2 %0, %1, %2, %0;" : "+l"(acc) : "l"(a), "l"(b));
}
__device__ __forceinline__ void unpack2(ull p, float& lo, float& hi) {
    asm("mov.b64 {%0, %1}, %2;" : "=f"(lo), "=f"(hi) : "l"(p));
}
// Store {v,v} as one 64-bit shared write (no MOV, no extra regs)
__device__ __forceinline__ void sts_dup(ull* p, float v) {
    unsigned sa = (unsigned)__cvta_generic_to_shared(p);
    asm volatile("st.shared.v2.f32 [%0], {%1, %1};" :: "r"(sa), "f"(v));
}

// ---------------------------------------------------------------------------
// Kernel 0: init — zero histogram, precompute ||e_k||^2 (fp32 fma chain)
// ---------------------------------------------------------------------------
__global__ void vq_init_kernel(const float* __restrict__ emb) {
    int t = threadIdx.x;
    if (t < KCB) {
        g_hist[t] = 0;
        const float4* e4 = (const float4*)(emb + t * DIM);
        float s = 0.f;
#pragma unroll
        for (int j = 0; j < 16; ++j) {
            float4 v = e4[j];
            s = fmaf(v.x, v.x, s);
            s = fmaf(v.y, v.y, s);
            s = fmaf(v.z, v.z, s);
            s = fmaf(v.w, v.w, s);
        }
        g_ne[t] = s;
    }
}

// ---------------------------------------------------------------------------
// Kernel A: argmin via tiled fp32 GEMM (FFMA2, e pre-duplicated in smem) +
// EMULATED reference rounding: dist = fl32(fl32(nx+ne) - fl32(2*s)),
// first-index argmin. Grid: 1024 blocks x 256 threads.
// Block = 64 positions x 512 codes, 4 chunks of 128 codes.
// Warp ry: positions ry*8..ry*8+7 (paired into f32x2 lanes).
// Lane cx: codes ch*128 + cx + {0,32,64,96}.
// ---------------------------------------------------------------------------
__global__ __launch_bounds__(256, 2) void vq_argmin_kernel(
    const float* __restrict__ x, const float* __restrict__ emb)
{
    __shared__ float Xs[64 * 64];      // [d][pos], d-major (pos pairs adjacent)
    __shared__ ull   Esd[128 * 65];    // [code][d] as {e,e} pairs, pad 65
    __shared__ float nes[KCB];         // ||e_k||^2 staged
    __shared__ float xpart[4 * 64];
    __shared__ float xn[64];           // ||x_p||^2 (binade-correct suffices)

    const int tid = threadIdx.x;
    const int posBase = blockIdx.x * 64;
    const int b  = posBase >> 10;       // 1024 positions per batch image
    const int hw = posBase & 1023;
    const float* xb = x + (size_t)b * 65536 + hw;  // + d*1024 + p

    // Load X tile (float4, coalesced): Xs[d*64+p]
#pragma unroll
    for (int it = 0; it < 4; ++it) {
        int j = it * 1024 + tid * 4;
        int d = j >> 6, p = j & 63;
        *(float4*)&Xs[d * 64 + p] = *(const float4*)&xb[d * 1024 + p];
    }
    // Stage ne
    nes[tid] = g_ne[tid];
    nes[tid + 256] = g_ne[tid + 256];
    __syncthreads();

    // nx per position
    {
        int p = tid & 63, g = tid >> 6;
        float s = 0.f;
#pragma unroll
        for (int j = 0; j < 16; ++j) {
            float v = Xs[(g * 16 + j) * 64 + p];
            s = fmaf(v, v, s);
        }
        xpart[g * 64 + p] = s;
    }
    __syncthreads();
    if (tid < 64) {
        xn[tid] = ((xpart[tid] + xpart[64 + tid]) + xpart[128 + tid]) + xpart[192 + tid];
    }

    const int ry = tid >> 5;
    const int cx = tid & 31;

    float best[8];
    int   bidx[8];
#pragma unroll
    for (int i = 0; i < 8; ++i) { best[i] = CUDART_INF_F; bidx[i] = 0; }

    float nx[8];   // filled after first sync below

    for (int ch = 0; ch < 4; ++ch) {
        __syncthreads();
        // Load E chunk (128 codes x 64 d) as duplicated pairs
#pragma unroll
        for (int it = 0; it < 8; ++it) {
            int j  = it * 1024 + tid * 4;
            int cc = j >> 6, d = j & 63;
            float4 e4 = *(const float4*)&emb[(ch * 128 + cc) * DIM + d];
            ull* row = &Esd[cc * 65 + d];
            sts_dup(row + 0, e4.x);
            sts_dup(row + 1, e4.y);
            sts_dup(row + 2, e4.z);
            sts_dup(row + 3, e4.w);
        }
        __syncthreads();

        if (ch == 0) {
#pragma unroll
            for (int i = 0; i < 8; ++i) nx[i] = xn[ry * 8 + i];
        }

        // acc[g][j]: code group g (k = ch*128+cx+32g), position pair j
        ull acc[4][4];
#pragma unroll
        for (int g = 0; g < 4; ++g)
#pragma unroll
            for (int j = 0; j < 4; ++j) acc[g][j] = 0ull;

#pragma unroll 16
        for (int d = 0; d < 64; ++d) {
            ull e0 = Esd[(cx      ) * 65 + d];   // LDS.64, conflict-free
            ull e1 = Esd[(cx + 32 ) * 65 + d];
            ull e2 = Esd[(cx + 64 ) * 65 + d];
            ull e3 = Esd[(cx + 96 ) * 65 + d];
            const ulonglong2 a0 = *(const ulonglong2*)&Xs[d * 64 + ry * 8];     // broadcast
            const ulonglong2 a1 = *(const ulonglong2*)&Xs[d * 64 + ry * 8 + 4];
            ffma2(acc[0][0], a0.x, e0); ffma2(acc[0][1], a0.y, e0);
            ffma2(acc[0][2], a1.x, e0); ffma2(acc[0][3], a1.y, e0);
            ffma2(acc[1][0], a0.x, e1); ffma2(acc[1][1], a0.y, e1);
            ffma2(acc[1][2], a1.x, e1); ffma2(acc[1][3], a1.y, e1);
            ffma2(acc[2][0], a0.x, e2); ffma2(acc[2][1], a0.y, e2);
            ffma2(acc[2][2], a1.x, e2); ffma2(acc[2][3], a1.y, e2);
            ffma2(acc[3][0], a0.x, e3); ffma2(acc[3][1], a0.y, e3);
            ffma2(acc[3][2], a1.x, e3); ffma2(acc[3][3], a1.y, e3);
        }

        // Epilogue: emulate jax rounding, running first-index argmin.
        // g ascending => code index ascending within thread.
#pragma unroll
        for (int g = 0; g < 4; ++g) {
            const int k = ch * 128 + cx + g * 32;
            const float ne = nes[k];
#pragma unroll
            for (int j = 0; j < 4; ++j) {
                float sa, sb;
                unpack2(acc[g][j], sa, sb);
                float da = __fsub_rn(__fadd_rn(nx[2 * j],     ne), __fmul_rn(2.0f, sa));
                float db = __fsub_rn(__fadd_rn(nx[2 * j + 1], ne), __fmul_rn(2.0f, sb));
                if (da < best[2 * j])     { best[2 * j]     = da; bidx[2 * j]     = k; }
                if (db < best[2 * j + 1]) { best[2 * j + 1] = db; bidx[2 * j + 1] = k; }
            }
        }
    }

    // Warp butterfly argmin per position (tie -> smaller index)
#pragma unroll
    for (int i = 0; i < 8; ++i) {
        float v = best[i];
        int   id = bidx[i];
#pragma unroll
        for (int off = 16; off > 0; off >>= 1) {
            float ov = __shfl_xor_sync(0xffffffffu, v, off);
            int   oi = __shfl_xor_sync(0xffffffffu, id, off);
            if (ov < v || (ov == v && oi < id)) { v = ov; id = oi; }
        }
        if (cx == 0) {
            int pos = posBase + ry * 8 + i;
            g_idx[pos] = id;
            atomicAdd(&g_hist[id], 1);
        }
    }
}

// ---------------------------------------------------------------------------
// Kernel B: gather + straight-through emulation + both layouts + loss partials.
// q_st = fl32(x + fl32(q - x)).
// Output layout: out[0]=loss, out[1..]=NCHW q_st, out[1+N]=perplexity,
//                out[2+N..]=flat NHWC q_st.
// ---------------------------------------------------------------------------
__global__ __launch_bounds__(256) void vq_output_kernel(
    const float* __restrict__ x, const float* __restrict__ emb,
    float* __restrict__ out)
{
    __shared__ float qs[128 * 65];   // tile [pos][d], pad 65
    __shared__ int   ks[128];
    __shared__ float red[256];

    const int tid = threadIdx.x;
    const int posBase = blockIdx.x * 128;
    const int b  = posBase >> 10;
    const int hw = posBase & 1023;

    if (tid < 128) ks[tid] = g_idx[posBase + tid];
    __syncthreads();

    float* out_nchw = out + 1;
    float* out_flat = out + 2 + NCHW_ELEMS;

    // Pass 1 (pos-major): coalesced codebook gather into smem
#pragma unroll
    for (int it = 0; it < 32; ++it) {
        int j = it * 256 + tid;
        int p = j >> 6, d = j & 63;
        qs[p * 65 + d] = emb[ks[p] * DIM + d];
    }
    __syncthreads();

    // Pass 2 (d-major): coalesced x read, NCHW q_st write, loss accumulation
    float lsum = 0.f;
#pragma unroll
    for (int it = 0; it < 32; ++it) {
        int j = it * 256 + tid;
        int d = j >> 7, p = j & 127;
        size_t g = (size_t)b * 65536 + (size_t)d * 1024 + hw + p;
        float q  = qs[p * 65 + d];
        float xv = x[g];
        float df  = __fsub_rn(q, xv);       // fl32(q - x)
        float qst = __fadd_rn(xv, df);      // fl32(x + (q - x))
        out_nchw[g] = qst;
        qs[p * 65 + d] = qst;
        lsum = fmaf(df, df, lsum);
    }
    __syncthreads();

    // Pass 3 (pos-major): flat NHWC q_st write (coalesced)
#pragma unroll
    for (int it = 0; it < 32; ++it) {
        int j = it * 256 + tid;
        int p = j >> 6, d = j & 63;
        out_flat[(size_t)(posBase + p) * DIM + d] = qs[p * 65 + d];
    }

    red[tid] = lsum;
    __syncthreads();
    for (int s = 128; s > 0; s >>= 1) {
        if (tid < s) red[tid] += red[tid + s];
        __syncthreads();
    }
    if (tid == 0) g_partial[blockIdx.x] = red[0];
}

// ---------------------------------------------------------------------------
// Kernel C: deterministic finalize — loss scalar + perplexity (all fp32).
// ---------------------------------------------------------------------------
__global__ void vq_finalize_kernel(float* __restrict__ out) {
    __shared__ float red[512];
    const int t = threadIdx.x;

    red[t] = g_partial[t];
    __syncthreads();
    for (int s = 256; s > 0; s >>= 1) {
        if (t < s) red[t] += red[t + s];
        __syncthreads();
    }
    if (t == 0) {
        out[0] = 1.25f * (red[0] / (float)NCHW_ELEMS);
    }
    __syncthreads();

    float p = (float)g_hist[t] * (1.0f / 65536.0f);
    red[t] = p * logf(p + 1e-10f);
    __syncthreads();
    for (int s = 256; s > 0; s >>= 1) {
        if (t < s) red[t] += red[t + s];
        __syncthreads();
    }
    if (t == 0) {
        out[NCHW_ELEMS + 1] = expf(-red[0]);
    }
}

// ---------------------------------------------------------------------------
extern "C" void kernel_launch(void* const* d_in, const int* in_sizes, int n_in,
                              void* d_out, int out_size) {
    const float* x   = (const float*)d_in[0];   // [64,64,32,32] f32 NCHW
    const float* emb = (const float*)d_in[1];   // [512,64] f32
    float* out = (float*)d_out;

    vq_init_kernel<<<1, 512>>>(emb);
    vq_argmin_kernel<<<1024, 256>>>(x, emb);
    vq_output_kernel<<<512, 256>>>(x, emb, out);
    vq_finalize_kernel<<<1, 512>>>(out);
}

// round 5
// speedup vs baseline: 1.3178x; 1.3178x over previous
#include <cuda_runtime.h>
#include <math_constants.h>

// Problem constants
#define NPOS 65536   // 64 * 32 * 32 positions
#define DIM  64      // embedding dim
#define KCB  512     // codebook size
#define NCHW_ELEMS 4194304  // 64*64*32*32

typedef unsigned long long ull;

// Scratch (allocation-free: __device__ globals)
__device__ int   g_idx[NPOS];
__device__ int   g_hist[KCB];
__device__ float g_ne[KCB];        // ||e_k||^2 in fp32
__device__ float g_partial[512];

// Packed fp32x2 FMA (Blackwell): per-lane IEEE identical to scalar fmaf.
__device__ __forceinline__ void ffma2(ull& acc, ull a, ull b) {
    asm("fma.rn.f32x2 %0, %1, %2, %0;" : "+l"(acc) : "l"(a), "l"(b));
}
__device__ __forceinline__ ull dup2(float v) {
    ull r;
    asm("mov.b64 %0, {%1, %1};" : "=l"(r) : "f"(v));
    return r;
}
__device__ __forceinline__ void unpack2(ull p, float& lo, float& hi) {
    asm("mov.b64 {%0, %1}, %2;" : "=f"(lo), "=f"(hi) : "l"(p));
}

// ---------------------------------------------------------------------------
// Kernel 0: init — zero histogram, precompute ||e_k||^2 (fp32 fma chain)
// ---------------------------------------------------------------------------
__global__ void vq_init_kernel(const float* __restrict__ emb) {
    int t = threadIdx.x;
    if (t < KCB) {
        g_hist[t] = 0;
        const float4* e4 = (const float4*)(emb + t * DIM);
        float s = 0.f;
#pragma unroll
        for (int j = 0; j < 16; ++j) {
            float4 v = e4[j];
            s = fmaf(v.x, v.x, s);
            s = fmaf(v.y, v.y, s);
            s = fmaf(v.z, v.z, s);
            s = fmaf(v.w, v.w, s);
        }
        g_ne[t] = s;
    }
}

// ---------------------------------------------------------------------------
// Kernel A: argmin via tiled fp32 GEMM (FFMA2, scalar-E smem + register dup)
// + EMULATED reference rounding: dist = fl32(fl32(nx+ne) - fl32(2*s)),
// first-index argmin. Grid: 1024 blocks x 256 threads.
// Block = 64 positions x 512 codes, 2 chunks of 128 codes (Es scalar floats).
// Warp ry: positions ry*8..ry*8+7 (paired into f32x2 lanes).
// Lane cx: codes ch*128 + cx + {0,32,64,96}.
// Crossbar budget/warp-d: 2 LDS.128 bcast + 4 scalar LDS = 6 wf per 32 FMA-cyc
// (0.75 of 128B/cyc at 4 warps/SMSP). Issue: 30/32. FMA pipe binds.
// ---------------------------------------------------------------------------
__global__ __launch_bounds__(256, 2) void vq_argmin_kernel(
    const float* __restrict__ x, const float* __restrict__ emb)
{
    __shared__ float Xs[64 * 64];      // [d][pos], d-major (pos pairs adjacent)
    __shared__ float Es[128 * 65];     // [code][d], scalar, pad 65 (conflict-free)
    __shared__ float nes[KCB];         // ||e_k||^2 staged
    __shared__ float xpart[4 * 64];
    __shared__ float xn[64];           // ||x_p||^2 (binade-correct suffices)

    const int tid = threadIdx.x;
    const int posBase = blockIdx.x * 64;
    const int b  = posBase >> 10;       // 1024 positions per batch image
    const int hw = posBase & 1023;
    const float* xb = x + (size_t)b * 65536 + hw;  // + d*1024 + p

    // Load X tile (float4, coalesced): Xs[d*64+p]
#pragma unroll
    for (int it = 0; it < 4; ++it) {
        int j = it * 1024 + tid * 4;
        int d = j >> 6, p = j & 63;
        *(float4*)&Xs[d * 64 + p] = *(const float4*)&xb[d * 1024 + p];
    }
    // Stage ne
    nes[tid] = g_ne[tid];
    nes[tid + 256] = g_ne[tid + 256];
    __syncthreads();

    // nx per position
    {
        int p = tid & 63, g = tid >> 6;
        float s = 0.f;
#pragma unroll
        for (int j = 0; j < 16; ++j) {
            float v = Xs[(g * 16 + j) * 64 + p];
            s = fmaf(v, v, s);
        }
        xpart[g * 64 + p] = s;
    }
    __syncthreads();
    if (tid < 64) {
        xn[tid] = ((xpart[tid] + xpart[64 + tid]) + xpart[128 + tid]) + xpart[192 + tid];
    }

    const int ry = tid >> 5;
    const int cx = tid & 31;

    float best[8];
    int   bidx[8];
#pragma unroll
    for (int i = 0; i < 8; ++i) { best[i] = CUDART_INF_F; bidx[i] = 0; }

    for (int ch = 0; ch < 4; ++ch) {
        __syncthreads();
        // Load E chunk (128 codes x 64 d), scalar stores (row pad 65 unaligned
        // for vector STS; LDG is float4-coalesced)
#pragma unroll
        for (int it = 0; it < 8; ++it) {
            int j  = it * 1024 + tid * 4;
            int cc = j >> 6, d = j & 63;
            float4 e4 = *(const float4*)&emb[(ch * 128 + cc) * DIM + d];
            float* row = &Es[cc * 65 + d];
            row[0] = e4.x; row[1] = e4.y; row[2] = e4.z; row[3] = e4.w;
        }
        __syncthreads();

        // acc[g][j]: code group g (k = ch*128+cx+32g), position pair j
        ull acc[4][4];
#pragma unroll
        for (int g = 0; g < 4; ++g)
#pragma unroll
            for (int j = 0; j < 4; ++j) acc[g][j] = 0ull;

#pragma unroll 16
        for (int d = 0; d < 64; ++d) {
            // scalar e loads: bank = (cx + d) % 32 -> conflict-free
            ull e0 = dup2(Es[(cx      ) * 65 + d]);
            ull e1 = dup2(Es[(cx + 32 ) * 65 + d]);
            ull e2 = dup2(Es[(cx + 64 ) * 65 + d]);
            ull e3 = dup2(Es[(cx + 96 ) * 65 + d]);
            // broadcast 128-bit shared loads: 4 packed position-pairs
            const ulonglong2 a0 = *(const ulonglong2*)&Xs[d * 64 + ry * 8];
            const ulonglong2 a1 = *(const ulonglong2*)&Xs[d * 64 + ry * 8 + 4];
            ffma2(acc[0][0], a0.x, e0); ffma2(acc[0][1], a0.y, e0);
            ffma2(acc[0][2], a1.x, e0); ffma2(acc[0][3], a1.y, e0);
            ffma2(acc[1][0], a0.x, e1); ffma2(acc[1][1], a0.y, e1);
            ffma2(acc[1][2], a1.x, e1); ffma2(acc[1][3], a1.y, e1);
            ffma2(acc[2][0], a0.x, e2); ffma2(acc[2][1], a0.y, e2);
            ffma2(acc[2][2], a1.x, e2); ffma2(acc[2][3], a1.y, e2);
            ffma2(acc[3][0], a0.x, e3); ffma2(acc[3][1], a0.y, e3);
            ffma2(acc[3][2], a1.x, e3); ffma2(acc[3][3], a1.y, e3);
        }

        // Epilogue: emulate jax rounding, running first-index argmin.
        // g ascending => code index ascending within thread.
#pragma unroll
        for (int g = 0; g < 4; ++g) {
            const int k = ch * 128 + cx + g * 32;
            const float ne = nes[k];
#pragma unroll
            for (int j = 0; j < 4; ++j) {
                float sa, sb;
                unpack2(acc[g][j], sa, sb);
                float nxa = xn[ry * 8 + 2 * j];        // smem broadcast (reg relief)
                float nxb = xn[ry * 8 + 2 * j + 1];
                float da = __fsub_rn(__fadd_rn(nxa, ne), __fmul_rn(2.0f, sa));
                float db = __fsub_rn(__fadd_rn(nxb, ne), __fmul_rn(2.0f, sb));
                if (da < best[2 * j])     { best[2 * j]     = da; bidx[2 * j]     = k; }
                if (db < best[2 * j + 1]) { best[2 * j + 1] = db; bidx[2 * j + 1] = k; }
            }
        }
    }

    // Warp butterfly argmin per position (tie -> smaller index)
#pragma unroll
    for (int i = 0; i < 8; ++i) {
        float v = best[i];
        int   id = bidx[i];
#pragma unroll
        for (int off = 16; off > 0; off >>= 1) {
            float ov = __shfl_xor_sync(0xffffffffu, v, off);
            int   oi = __shfl_xor_sync(0xffffffffu, id, off);
            if (ov < v || (ov == v && oi < id)) { v = ov; id = oi; }
        }
        if (cx == 0) {
            int pos = posBase + ry * 8 + i;
            g_idx[pos] = id;
            atomicAdd(&g_hist[id], 1);
        }
    }
}

// ---------------------------------------------------------------------------
// Kernel B: gather + straight-through emulation + both layouts + loss partials.
// q_st = fl32(x + fl32(q - x)).
// Output layout: out[0]=loss, out[1..]=NCHW q_st, out[1+N]=perplexity,
//                out[2+N..]=flat NHWC q_st.
// ---------------------------------------------------------------------------
__global__ __launch_bounds__(256) void vq_output_kernel(
    const float* __restrict__ x, const float* __restrict__ emb,
    float* __restrict__ out)
{
    __shared__ float qs[128 * 65];   // tile [pos][d], pad 65
    __shared__ int   ks[128];
    __shared__ float red[256];

    const int tid = threadIdx.x;
    const int posBase = blockIdx.x * 128;
    const int b  = posBase >> 10;
    const int hw = posBase & 1023;

    if (tid < 128) ks[tid] = g_idx[posBase + tid];
    __syncthreads();

    float* out_nchw = out + 1;
    float* out_flat = out + 2 + NCHW_ELEMS;

    // Pass 1 (pos-major): coalesced codebook gather into smem
#pragma unroll
    for (int it = 0; it < 32; ++it) {
        int j = it * 256 + tid;
        int p = j >> 6, d = j & 63;
        qs[p * 65 + d] = emb[ks[p] * DIM + d];
    }
    __syncthreads();

    // Pass 2 (d-major): coalesced x read, NCHW q_st write, loss accumulation
    float lsum = 0.f;
#pragma unroll
    for (int it = 0; it < 32; ++it) {
        int j = it * 256 + tid;
        int d = j >> 7, p = j & 127;
        size_t g = (size_t)b * 65536 + (size_t)d * 1024 + hw + p;
        float q  = qs[p * 65 + d];
        float xv = x[g];
        float df  = __fsub_rn(q, xv);       // fl32(q - x)
        float qst = __fadd_rn(xv, df);      // fl32(x + (q - x))
        out_nchw[g] = qst;
        qs[p * 65 + d] = qst;
        lsum = fmaf(df, df, lsum);
    }
    __syncthreads();

    // Pass 3 (pos-major): flat NHWC q_st write (coalesced)
#pragma unroll
    for (int it = 0; it < 32; ++it) {
        int j = it * 256 + tid;
        int p = j >> 6, d = j & 63;
        out_flat[(size_t)(posBase + p) * DIM + d] = qs[p * 65 + d];
    }

    red[tid] = lsum;
    __syncthreads();
    for (int s = 128; s > 0; s >>= 1) {
        if (tid < s) red[tid] += red[tid + s];
        __syncthreads();
    }
    if (tid == 0) g_partial[blockIdx.x] = red[0];
}

// ---------------------------------------------------------------------------
// Kernel C: deterministic finalize — loss scalar + perplexity (all fp32).
// ---------------------------------------------------------------------------
__global__ void vq_finalize_kernel(float* __restrict__ out) {
    __shared__ float red[512];
    const int t = threadIdx.x;

    red[t] = g_partial[t];
    __syncthreads();
    for (int s = 256; s > 0; s >>= 1) {
        if (t < s) red[t] += red[t + s];
        __syncthreads();
    }
    if (t == 0) {
        out[0] = 1.25f * (red[0] / (float)NCHW_ELEMS);
    }
    __syncthreads();

    float p = (float)g_hist[t] * (1.0f / 65536.0f);
    red[t] = p * logf(p + 1e-10f);
    __syncthreads();
    for (int s = 256; s > 0; s >>= 1) {
        if (t < s) red[t] += red[t + s];
        __syncthreads();
    }
    if (t == 0) {
        out[NCHW_ELEMS + 1] = expf(-red[0]);
    }
}

// ---------------------------------------------------------------------------
extern "C" void kernel_launch(void* const* d_in, const int* in_sizes, int n_in,
                              void* d_out, int out_size) {
    const float* x   = (const float*)d_in[0];   // [64,64,32,32] f32 NCHW
    const float* emb = (const float*)d_in[1];   // [512,64] f32
    float* out = (float*)d_out;

    vq_init_kernel<<<1, 512>>>(emb);
    vq_argmin_kernel<<<1024, 256>>>(x, emb);
    vq_output_kernel<<<512, 256>>>(x, emb, out);
    vq_finalize_kernel<<<1, 512>>>(out);
}